// round 6
// baseline (speedup 1.0000x reference)
#include <cuda_runtime.h>
#include <cstdint>

// BoundarySeg: out[b,j,0:768]   = sum_{d=0..5} w[b,j,d] * hidden[b, min(j+d,L-1), :]
//              out[b,j,768:1536]= hidden[b,j,:] * sum_d w[b,j,d]
// w[b,j,d] = span_adjacency[b, j, j+d] if j+d < L else 0.
// B=16, L=1024, H=768. fp32.
//
// R6: double-buffered TMA-in. Each CTA owns 8 j's as TWO 4-j tiles with
// independent 9-row input buffers; both bulk copies are issued up-front so
// tile-1's DMA overlaps tile-0's compute/stores. Sliding register window +
// direct streaming STG.128 out (best path from R2/R5).

#define BB 16
#define LL 1024
#define HH 768
#define HV (HH / 4)            // 192 float4 per row
#define TJ 4                   // j's per tile
#define NT 2                   // tiles per CTA
#define SPAN 6
#define NROWS (TJ + SPAN - 1)  // 9 rows per tile

__device__ __forceinline__ uint32_t smem_u32(const void* p) {
    uint32_t a;
    asm("{ .reg .u64 t; cvta.to.shared.u64 t, %1; cvt.u32.u64 %0, t; }"
        : "=r"(a) : "l"(p));
    return a;
}

__device__ __forceinline__ void stcs4(float4* p, float4 v) {
    asm volatile("st.global.cs.v4.f32 [%0], {%1,%2,%3,%4};"
                 :: "l"(p), "f"(v.x), "f"(v.y), "f"(v.z), "f"(v.w) : "memory");
}

struct __align__(16) SmemLayout {
    float4   in[NT][NROWS * HV];   // 2 x 27648 B
    float    w[NT][TJ * SPAN];     // 2 x 96 B
    uint64_t mbar[NT];
};

__global__ __launch_bounds__(HV)
void boundary_seg_kernel(const float* __restrict__ adj,
                         const float* __restrict__ hid,
                         float* __restrict__ out)
{
    extern __shared__ __align__(16) char smem_raw[];
    SmemLayout* sm = reinterpret_cast<SmemLayout*>(smem_raw);

    const int tile = blockIdx.x;           // b * 128 + group-of-8-j
    const int b  = tile >> 7;
    const int j0 = (tile & 127) * (TJ * NT);
    const int t  = threadIdx.x;            // float4 column of H

    if (t == 0) {
#pragma unroll
        for (int k = 0; k < NT; k++)
            asm volatile("mbarrier.init.shared::cta.b64 [%0], %1;"
                         :: "r"(smem_u32(&sm->mbar[k])), "r"(1) : "memory");
    }
    __syncthreads();

    // Issue BOTH input bulk-copies immediately (independent buffers).
    if (t == 0) {
#pragma unroll
        for (int k = 0; k < NT; k++) {
            const int js = j0 + k * TJ;
            const int rl = min(NROWS, LL - js);
            const uint32_t nbytes = (uint32_t)rl * HH * 4u;
            const uint32_t s_mb = smem_u32(&sm->mbar[k]);
            asm volatile("mbarrier.arrive.expect_tx.shared::cta.b64 _, [%0], %1;"
                         :: "r"(s_mb), "r"(nbytes) : "memory");
            const float* src = hid + ((size_t)b * LL + js) * HH;
            asm volatile(
                "cp.async.bulk.shared::cluster.global.mbarrier::complete_tx::bytes "
                "[%0], [%1], %2, [%3];"
                :: "r"(smem_u32(sm->in[k])), "l"(src), "r"(nbytes), "r"(s_mb)
                : "memory");
        }
    }

    // Weights for both tiles: 48 scattered L2 loads, overlapped with the DMAs.
    if (t < NT * TJ * SPAN) {
        const int k  = t / (TJ * SPAN);
        const int r  = t - k * (TJ * SPAN);
        const int jj = r / SPAN;
        const int d  = r - jj * SPAN;
        const int j  = j0 + k * TJ + jj;
        const int col = j + d;
        float w = 0.0f;
        if (col < LL)
            w = __ldg(adj + ((size_t)b * LL + j) * LL + col);
        sm->w[k][jj * SPAN + d] = w;
    }
    __syncthreads();

    float4* __restrict__ out4 = reinterpret_cast<float4*>(out);

#pragma unroll
    for (int k = 0; k < NT; k++) {
        const int js = j0 + k * TJ;
        const int rl = min(NROWS, LL - js);
        const int rmax = rl - 1;

        // Wait for this tile's bulk copy (tile 1 streams in during tile 0).
        {
            const uint32_t s_mb = smem_u32(&sm->mbar[k]);
            uint32_t done;
            do {
                asm volatile(
                    "{ .reg .pred p;\n\t"
                    "  mbarrier.try_wait.parity.shared::cta.b64 p, [%1], %2, 10000000;\n\t"
                    "  selp.b32 %0, 1, 0, p; }"
                    : "=r"(done) : "r"(s_mb), "r"(0u) : "memory");
            } while (!done);
        }

        const float4* __restrict__ buf = sm->in[k];
        const float*  __restrict__ wk  = sm->w[k];

        // Sliding register window of 6 rows.
        float4 v[SPAN];
#pragma unroll
        for (int d = 0; d < SPAN; d++)
            v[d] = buf[min(d, rmax) * HV + t];

#pragma unroll
        for (int jj = 0; jj < TJ; jj++) {
            const float w0 = wk[jj * SPAN + 0], w1 = wk[jj * SPAN + 1];
            const float w2 = wk[jj * SPAN + 2], w3 = wk[jj * SPAN + 3];
            const float w4 = wk[jj * SPAN + 4], w5 = wk[jj * SPAN + 5];
            const float wsum = ((w0 + w1) + (w2 + w3)) + (w4 + w5);

            float4 f;
            f.x = w0 * v[0].x; f.y = w0 * v[0].y;
            f.z = w0 * v[0].z; f.w = w0 * v[0].w;
            f.x = fmaf(w1, v[1].x, f.x); f.y = fmaf(w1, v[1].y, f.y);
            f.z = fmaf(w1, v[1].z, f.z); f.w = fmaf(w1, v[1].w, f.w);
            f.x = fmaf(w2, v[2].x, f.x); f.y = fmaf(w2, v[2].y, f.y);
            f.z = fmaf(w2, v[2].z, f.z); f.w = fmaf(w2, v[2].w, f.w);
            f.x = fmaf(w3, v[3].x, f.x); f.y = fmaf(w3, v[3].y, f.y);
            f.z = fmaf(w3, v[3].z, f.z); f.w = fmaf(w3, v[3].w, f.w);
            f.x = fmaf(w4, v[4].x, f.x); f.y = fmaf(w4, v[4].y, f.y);
            f.z = fmaf(w4, v[4].z, f.z); f.w = fmaf(w4, v[4].w, f.w);
            f.x = fmaf(w5, v[5].x, f.x); f.y = fmaf(w5, v[5].y, f.y);
            f.z = fmaf(w5, v[5].z, f.z); f.w = fmaf(w5, v[5].w, f.w);

            float4 s;
            s.x = v[0].x * wsum; s.y = v[0].y * wsum;
            s.z = v[0].z * wsum; s.w = v[0].w * wsum;

            const size_t obase =
                ((size_t)b * LL + (js + jj)) * (size_t)(2 * HV);
            stcs4(out4 + obase + t, f);
            stcs4(out4 + obase + HV + t, s);

            // Slide the window.
#pragma unroll
            for (int d = 0; d < SPAN - 1; d++) v[d] = v[d + 1];
            v[SPAN - 1] = buf[min(jj + SPAN, rmax) * HV + t];
        }
    }
}

extern "C" void kernel_launch(void* const* d_in, const int* in_sizes, int n_in,
                              void* d_out, int out_size)
{
    const float* adj = (const float*)d_in[0];   // (B,L,L,1)
    const float* hid = (const float*)d_in[1];   // (B,L,H)
    float* out = (float*)d_out;                 // (B,L,2H)

    const int smem_bytes = (int)sizeof(SmemLayout);
    static bool attr_set = false;
    if (!attr_set) {
        cudaFuncSetAttribute(boundary_seg_kernel,
                             cudaFuncAttributeMaxDynamicSharedMemorySize,
                             smem_bytes);
        attr_set = true;
    }

    const int grid = BB * (LL / (TJ * NT));     // 2048 CTAs
    boundary_seg_kernel<<<grid, HV, smem_bytes>>>(adj, hid, out);
}